// round 8
// baseline (speedup 1.0000x reference)
#include <cuda_runtime.h>
#include <cstdint>

// Problem constants (fixed shapes per reference)
#define DIN    768
#define DSAE   16384
#define TDIM   12
#define KTOP   64
#define KBASIS 3
#define BSZ    1024
#define KDIM   9216

// GEMM tiling: CTA 128x256, 512 threads (16 warps, 2M x 8N, warp tile 64x32)
#define KCH      16
#define NCHUNK   (KDIM / KCH)     // 576
#define NSTAGE   3
#define A_PITCH  20               // floats per A smem row (bank-exact)
#define B_PITCH  264              // floats per B smem row (264 mod 32 == 8)
#define A_ST_F   (128 * A_PITCH)  // 2560 floats
#define B_ST_F   (16 * B_PITCH)   // 4224 floats
#define STAGE_F  (A_ST_F + B_ST_F)         // 6784 floats
#define STAGE_B  (STAGE_F * 4)             // 27136 bytes
#define SMEM_B   (NSTAGE * STAGE_B)        // 81408 bytes

// band half-width around approx 64th value (~40 sigma of tf32 RNA noise)
#define DELTA  0.03f
#define MAXB   64

// round fp32 bits to nearest tf32 (MMA truncates low 13 bits; +bit12 = RNA)
#define TF32RND(u) ((u) + 0x1000u)

// ---------------------------------------------------------------------------
// Device scratch
// ---------------------------------------------------------------------------
__device__ float g_pre[(size_t)BSZ * DSAE];      // 64 MB
__device__ int   g_idx[BSZ * KTOP];
__device__ float g_val[BSZ * KTOP];
__device__ int   g_scnt[BSZ];                    // certain count per row
__device__ int   g_bcnt[BSZ];                    // band count per row
__device__ int   g_bidx[BSZ][MAXB];              // band candidate indices
__device__ float g_bval[BSZ][MAXB];              // exact rescored values

// ---------------------------------------------------------------------------
// helpers
// ---------------------------------------------------------------------------
__device__ __forceinline__ uint32_t smem_u32(const void* p) {
    uint32_t a;
    asm("{ .reg .u64 t; cvta.to.shared.u64 t, %1; cvt.u32.u64 %0, t; }" : "=r"(a) : "l"(p));
    return a;
}

#define CP16(sa, ga) \
    asm volatile("cp.async.cg.shared.global [%0], [%1], 16;" :: "r"(sa), "l"(ga))
#define CP_COMMIT()  asm volatile("cp.async.commit_group;")
#define CP_WAIT1()   asm volatile("cp.async.wait_group 1;")
#define CP_WAIT0()   asm volatile("cp.async.wait_group 0;")

__device__ __forceinline__ void mma8(float* c, const uint32_t* a, const uint32_t* b) {
    asm volatile(
        "mma.sync.aligned.m16n8k8.row.col.f32.tf32.tf32.f32 "
        "{%0,%1,%2,%3}, {%4,%5,%6,%7}, {%8,%9}, {%0,%1,%2,%3};\n"
        : "+f"(c[0]), "+f"(c[1]), "+f"(c[2]), "+f"(c[3])
        : "r"(a[0]), "r"(a[1]), "r"(a[2]), "r"(a[3]), "r"(b[0]), "r"(b[1]));
}

// ---------------------------------------------------------------------------
// Kernel 1: single-pass tf32 mma.sync GEMM, cp.async producer.
//   pre[1024,16384] = x[1024,9216] @ W_enc[9216,16384] + b_enc
// FIX vs R6/R7: A smem is stored CONTIGUOUS in k (cp.async direct copy), so
// the A fragment must load canonical k-offsets {t, t+4} x {row, row+8}
// (scalar LDS, conflict-free with pitch 20). R6/R7 kept the R5 float2 read
// at 2t -> A carried k={2t,2t+1} vs B's k={t,t+4}: a k-permuted mismatch
// product. Fragments rounded to nearest tf32 via +0x1000 (zero-mean noise).
// ---------------------------------------------------------------------------
__global__ __launch_bounds__(512, 1)
void enc_gemm(const float* __restrict__ A,
              const float* __restrict__ B,
              const float* __restrict__ bias)
{
    extern __shared__ float sm[];
    const uint32_t sbase = smem_u32(sm);

    const int tid  = threadIdx.x;
    const int wid  = tid >> 5;
    const int lane = tid & 31;
    const int by   = blockIdx.x;   // M tile (0..7)   -- fast-varying for B reuse
    const int bx   = blockIdx.y;   // N tile (0..63)

    const int wm = wid >> 3;       // 0..1  (64-row half)
    const int wn = wid & 7;        // 0..7  (32-col slice)
    const int g  = lane >> 2;      // 0..7
    const int t  = lane & 3;       // 0..3

    // producer smem byte offsets (within a stage)
    const uint32_t aoff  = (uint32_t)(tid >> 2) * (A_PITCH * 4) + (uint32_t)(tid & 3) * 16;
    const uint32_t boff0 = (uint32_t)(A_ST_F * 4) + (uint32_t)(tid >> 6) * (B_PITCH * 4)
                         + (uint32_t)(tid & 63) * 16;
    const uint32_t boff1 = boff0 + 8u * (B_PITCH * 4);

    // producer gmem base pointers (k = 0)
    const float* gA = A + ((size_t)by * 128 + (tid >> 2)) * KDIM + (tid & 3) * 4;
    const float* gB = B + (size_t)(tid >> 6) * DSAE + (size_t)bx * 256 + (tid & 63) * 4;

#define ISSUE(stage, c)                                                      \
    do {                                                                     \
        const uint32_t _sb = sbase + (uint32_t)(stage) * STAGE_B;            \
        const int _k0 = (c) * KCH;                                           \
        CP16(_sb + aoff, gA + _k0);                                          \
        const float* _gb = gB + (size_t)_k0 * DSAE;                          \
        CP16(_sb + boff0, _gb);                                              \
        CP16(_sb + boff1, _gb + (size_t)8 * DSAE);                           \
        CP_COMMIT();                                                         \
    } while (0)

    float acc[4][4][4];
#pragma unroll
    for (int mt = 0; mt < 4; mt++)
#pragma unroll
        for (int nt = 0; nt < 4; nt++)
#pragma unroll
            for (int q = 0; q < 4; q++) acc[mt][nt][q] = 0.f;

    ISSUE(0, 0);
    ISSUE(1, 1);

    int st = 0;
    for (int c = 0; c < NCHUNK; c++) {
        CP_WAIT1();
        __syncthreads();

        if (c + 2 < NCHUNK) {
            int ns = st + 2; if (ns >= NSTAGE) ns -= NSTAGE;
            ISSUE(ns, c + 2);
        }

        const float* As = sm + (size_t)st * STAGE_F;
        const float* Bs = As + A_ST_F;
#pragma unroll
        for (int ks = 0; ks < 2; ks++) {
            uint32_t Af[4][4], Bf[4][2];
#pragma unroll
            for (int mt = 0; mt < 4; mt++) {
                // canonical m16n8k8 A fragment: k = t, t+4 ; rows g, g+8
                const int r0 = (wm * 64 + mt * 16 + g) * A_PITCH + ks * 8 + t;
                Af[mt][0] = TF32RND(__float_as_uint(As[r0]));
                Af[mt][1] = TF32RND(__float_as_uint(As[r0 + 8 * A_PITCH]));
                Af[mt][2] = TF32RND(__float_as_uint(As[r0 + 4]));
                Af[mt][3] = TF32RND(__float_as_uint(As[r0 + 8 * A_PITCH + 4]));
            }
#pragma unroll
            for (int nt = 0; nt < 4; nt++) {
                // canonical B fragment: k = t, t+4 ; col g
                const int cb = (ks * 8 + t) * B_PITCH + wn * 32 + nt * 8 + g;
                Bf[nt][0] = TF32RND(__float_as_uint(Bs[cb]));
                Bf[nt][1] = TF32RND(__float_as_uint(Bs[cb + 4 * B_PITCH]));
            }
#pragma unroll
            for (int mt = 0; mt < 4; mt++)
#pragma unroll
                for (int nt = 0; nt < 4; nt++)
                    mma8(acc[mt][nt], Af[mt], Bf[nt]);
        }

        if (++st >= NSTAGE) st = 0;
    }
    CP_WAIT0();

    // ---- epilogue: +bias, store to g_pre ----
#pragma unroll
    for (int nt = 0; nt < 4; nt++) {
        const int col = bx * 256 + wn * 32 + nt * 8 + 2 * t;
        const float b0 = bias[col], b1 = bias[col + 1];
#pragma unroll
        for (int mt = 0; mt < 4; mt++) {
            const size_t r0 = (size_t)(by * 128 + wm * 64 + mt * 16 + g) * DSAE + col;
            *(float2*)(g_pre + r0) =
                make_float2(acc[mt][nt][0] + b0, acc[mt][nt][1] + b1);
            *(float2*)(g_pre + r0 + (size_t)8 * DSAE) =
                make_float2(acc[mt][nt][2] + b0, acc[mt][nt][3] + b1);
        }
    }
}

// ---------------------------------------------------------------------------
// Kernel 2: per-row top-64 radix select on approx pre + certain/band split
// ---------------------------------------------------------------------------
__device__ __forceinline__ unsigned f2k(float f) {
    unsigned u = __float_as_uint(f);
    return (u & 0x80000000u) ? ~u : (u | 0x80000000u);
}
__device__ __forceinline__ float k2f(unsigned k) {
    unsigned u = (k & 0x80000000u) ? (k & 0x7fffffffu) : ~k;
    return __uint_as_float(u);
}

__global__ void topk_kernel(float* __restrict__ z_out)
{
    extern __shared__ unsigned skeys[];          // DSAE * 4 = 64 KB
    __shared__ unsigned hist[256];
    __shared__ int s_digit, s_take, s_cnt;

    const int b   = blockIdx.x;
    const int tid = threadIdx.x;
    const float* row = g_pre + (size_t)b * DSAE;

    for (int e = tid; e < DSAE; e += 256) skeys[e] = f2k(row[e]);
    if (tid == 0) { s_cnt = 0; g_bcnt[b] = 0; }
    __syncthreads();

    unsigned prefix = 0;
    int k_rem = KTOP;
#pragma unroll
    for (int r = 0; r < 4; r++) {
        const int shift = 24 - 8 * r;
        hist[tid] = 0;
        __syncthreads();
        for (int e = tid; e < DSAE; e += 256) {
            const unsigned key = skeys[e];
            if (r == 0 || (key >> (shift + 8)) == prefix)
                atomicAdd(&hist[(key >> shift) & 255u], 1u);
        }
        __syncthreads();
        if (tid == 0) {
            int c = 0, d;
            for (d = 255; d > 0; --d) {
                const int h = (int)hist[d];
                if (c + h >= k_rem) break;
                c += h;
            }
            s_digit = d;
            s_take  = k_rem - c;
        }
        __syncthreads();
        prefix = (prefix << 8) | (unsigned)s_digit;
        k_rem  = s_take;
        __syncthreads();
    }

    const float kv     = k2f(prefix);   // approx 64th-largest value
    const float hi_thr = kv + DELTA;
    const float lo_thr = kv - DELTA;

    for (int e = tid; e < DSAE; e += 256) {
        const float v = k2f(skeys[e]);
        if (v > hi_thr) {
            // certainly in exact top-64 (approx error << DELTA)
            const float zv = fmaxf(v, 0.f);
            z_out[(size_t)b * DSAE + e] = zv;
            const int p = atomicAdd(&s_cnt, 1);
            g_idx[b * KTOP + p] = e;
            g_val[b * KTOP + p] = zv;
        } else {
            z_out[(size_t)b * DSAE + e] = 0.f;   // band entries fixed up later
            if (v >= lo_thr) {
                const int q = atomicAdd(&g_bcnt[b], 1);
                if (q < MAXB) g_bidx[b][q] = e;
            }
        }
    }
    __syncthreads();
    if (tid == 0) g_scnt[b] = s_cnt;
}

// ---------------------------------------------------------------------------
// Kernel 3: exact rescoring of band candidates
// ---------------------------------------------------------------------------
__global__ __launch_bounds__(256)
void rescore_kernel(const float* __restrict__ x,
                    const float* __restrict__ W,
                    const float* __restrict__ bias)
{
    const int slot = blockIdx.x;
    const int b    = blockIdx.y;
    int cnt = g_bcnt[b];
    if (cnt > MAXB) cnt = MAXB;
    if (slot >= cnt) return;

    __shared__ float wsum[8];
    const int tid  = threadIdx.x;
    const int col  = g_bidx[b][slot];
    const float* xr = x + (size_t)b * KDIM;
    const float* wc = W + col;

    float s = 0.f;
#pragma unroll
    for (int i = 0; i < KDIM / 256; i++) {
        const int k = tid + i * 256;
        s = fmaf(xr[k], __ldg(&wc[(size_t)k * DSAE]), s);
    }
#pragma unroll
    for (int o = 16; o > 0; o >>= 1) s += __shfl_down_sync(0xffffffffu, s, o);
    if ((tid & 31) == 0) wsum[tid >> 5] = s;
    __syncthreads();
    if (tid == 0) {
        float tot = 0.f;
#pragma unroll
        for (int w = 0; w < 8; w++) tot += wsum[w];
        g_bval[b][slot] = tot + bias[col];
    }
}

// ---------------------------------------------------------------------------
// Kernel 4: fixup — rank band entries by exact score, fill remaining slots
// ---------------------------------------------------------------------------
__global__ __launch_bounds__(MAXB)
void fixup_kernel(float* __restrict__ z_out)
{
    __shared__ int   bi[MAXB];
    __shared__ float bv[MAXB];

    const int b   = blockIdx.x;
    const int tid = threadIdx.x;
    int cnt = g_bcnt[b];
    if (cnt > MAXB) cnt = MAXB;
    const int scnt = g_scnt[b];
    const int rem  = KTOP - scnt;

    if (tid < cnt) { bi[tid] = g_bidx[b][tid]; bv[tid] = g_bval[b][tid]; }
    __syncthreads();

    if (tid < cnt) {
        const int   mi = bi[tid];
        const float mv = bv[tid];
        int rank = 0;
        for (int j = 0; j < cnt; j++)
            rank += (bv[j] > mv) || (bv[j] == mv && bi[j] < mi);
        if (rank < rem) {
            const float zv = fmaxf(mv, 0.f);
            z_out[(size_t)b * DSAE + mi] = zv;
            const int pos = scnt + rank;
            g_idx[b * KTOP + pos] = mi;
            g_val[b * KTOP + pos] = zv;
        }
    }
}

// ---------------------------------------------------------------------------
// Kernel 5: sparse decode + basis combine + x_hat + loss
// ---------------------------------------------------------------------------
__global__ __launch_bounds__(256)
void decode_kernel(const float* __restrict__ x,
                   const float* __restrict__ Wb,
                   const float* __restrict__ alpha,
                   const float* __restrict__ b_dec,
                   float* __restrict__ xhat,
                   float* __restrict__ loss)
{
    __shared__ int   sidx[KTOP];
    __shared__ float sval[KTOP];
    __shared__ float salpha[TDIM * KBASIS];
    __shared__ float warpsum[8];

    const int b = blockIdx.x, tid = threadIdx.x;
    if (tid < KTOP)          { sidx[tid] = g_idx[b * KTOP + tid]; sval[tid] = g_val[b * KTOP + tid]; }
    if (tid < TDIM * KBASIS) { salpha[tid] = alpha[tid]; }
    __syncthreads();

    float acc[KBASIS][3];
#pragma unroll
    for (int k3 = 0; k3 < KBASIS; k3++)
#pragma unroll
        for (int dd = 0; dd < 3; dd++) acc[k3][dd] = 0.f;

    for (int j = 0; j < KTOP; j++) {
        const float v = sval[j];
        if (v == 0.f) continue;
        const int s = sidx[j];
        const float* wr = Wb + (size_t)s * DIN;
#pragma unroll
        for (int k3 = 0; k3 < KBASIS; k3++) {
            const float* w = wr + (size_t)k3 * DSAE * DIN;
#pragma unroll
            for (int dd = 0; dd < 3; dd++)
                acc[k3][dd] = fmaf(v, __ldg(&w[tid + dd * 256]), acc[k3][dd]);
        }
    }

    float lsum = 0.f;
#pragma unroll
    for (int t = 0; t < TDIM; t++) {
        const float a0 = salpha[t * KBASIS + 0];
        const float a1 = salpha[t * KBASIS + 1];
        const float a2 = salpha[t * KBASIS + 2];
#pragma unroll
        for (int dd = 0; dd < 3; dd++) {
            const int d = tid + dd * 256;
            const size_t off = ((size_t)b * TDIM + t) * DIN + d;
            const float xh = a0 * acc[0][dd] + a1 * acc[1][dd] + a2 * acc[2][dd]
                           + b_dec[t * DIN + d];
            xhat[off] = xh;
            const float diff = xh - x[off];
            lsum = fmaf(diff, diff, lsum);
        }
    }

#pragma unroll
    for (int o = 16; o > 0; o >>= 1) lsum += __shfl_down_sync(0xffffffffu, lsum, o);
    if ((tid & 31) == 0) warpsum[tid >> 5] = lsum;
    __syncthreads();
    if (tid == 0) {
        float s = 0.f;
#pragma unroll
        for (int w = 0; w < 8; w++) s += warpsum[w];
        atomicAdd(loss, s * (1.0f / (float)(BSZ * TDIM)));
    }
}

// ---------------------------------------------------------------------------
// kernel_launch: inputs = [x, W_enc, b_enc, W_base, alpha, b_dec, k]
// output (f32, concat): [recon_loss(1), x_hat(B*T*DIN), z(B*DSAE)]
// ---------------------------------------------------------------------------
extern "C" void kernel_launch(void* const* d_in, const int* in_sizes, int n_in,
                              void* d_out, int out_size)
{
    const float* x      = (const float*)d_in[0];
    const float* W_enc  = (const float*)d_in[1];
    const float* b_enc  = (const float*)d_in[2];
    const float* W_base = (const float*)d_in[3];
    const float* alpha  = (const float*)d_in[4];
    const float* b_dec  = (const float*)d_in[5];

    float* out  = (float*)d_out;
    float* loss = out;
    float* xhat = out + 1;
    float* z    = out + 1 + (size_t)BSZ * TDIM * DIN;

    cudaMemsetAsync(loss, 0, sizeof(float));

    cudaFuncSetAttribute(enc_gemm,
                         cudaFuncAttributeMaxDynamicSharedMemorySize, SMEM_B);
    dim3 gemm_grid(BSZ / 128, DSAE / 256);   // (8, 64): M fast-varying
    enc_gemm<<<gemm_grid, 512, SMEM_B>>>(x, W_enc, b_enc);

    cudaFuncSetAttribute(topk_kernel,
                         cudaFuncAttributeMaxDynamicSharedMemorySize,
                         DSAE * (int)sizeof(unsigned));
    topk_kernel<<<BSZ, 256, DSAE * sizeof(unsigned)>>>(z);

    rescore_kernel<<<dim3(MAXB, BSZ), 256>>>(x, W_enc, b_enc);
    fixup_kernel<<<BSZ, MAXB>>>(z);

    decode_kernel<<<BSZ, 256>>>(x, W_base, alpha, b_dec, xhat, loss);
}

// round 9
// speedup vs baseline: 1.0410x; 1.0410x over previous
#include <cuda_runtime.h>
#include <cstdint>

// Problem constants (fixed shapes per reference)
#define DIN    768
#define DSAE   16384
#define TDIM   12
#define KTOP   64
#define KBASIS 3
#define BSZ    1024
#define KDIM   9216

// GEMM tiling: CTA 128x256, 256 threads (8 warps, 2M x 4N, warp tile 64x64)
#define KCH      16
#define NCHUNK   (KDIM / KCH)     // 576
#define NSTAGE   3
#define A_PITCH  20               // floats per A smem row (bank-exact)
#define B_PITCH  264              // floats per B smem row (264 mod 32 == 8)
#define A_ST_F   (128 * A_PITCH)  // 2560 floats
#define B_ST_F   (16 * B_PITCH)   // 4224 floats
#define STAGE_F  (A_ST_F + B_ST_F)         // 6784 floats
#define STAGE_B  (STAGE_F * 4)             // 27136 bytes
#define SMEM_B   (NSTAGE * STAGE_B)        // 81408 bytes

// band half-width around approx 64th value (~40 sigma of tf32 RNA noise)
#define DELTA  0.03f
#define MAXB   64

// round fp32 bits to nearest tf32 (MMA truncates low 13 bits; +bit12 = RNA)
#define TF32RND(u) ((u) + 0x1000u)

// ---------------------------------------------------------------------------
// Device scratch
// ---------------------------------------------------------------------------
__device__ float g_pre[(size_t)BSZ * DSAE];      // 64 MB
__device__ int   g_idx[BSZ * KTOP];
__device__ float g_val[BSZ * KTOP];
__device__ int   g_scnt[BSZ];                    // certain count per row
__device__ int   g_bcnt[BSZ];                    // band count per row
__device__ int   g_bidx[BSZ][MAXB];              // band candidate indices
__device__ float g_bval[BSZ][MAXB];              // exact rescored values

// ---------------------------------------------------------------------------
// helpers
// ---------------------------------------------------------------------------
__device__ __forceinline__ uint32_t smem_u32(const void* p) {
    uint32_t a;
    asm("{ .reg .u64 t; cvta.to.shared.u64 t, %1; cvt.u32.u64 %0, t; }" : "=r"(a) : "l"(p));
    return a;
}

#define CP16(sa, ga) \
    asm volatile("cp.async.cg.shared.global [%0], [%1], 16;" :: "r"(sa), "l"(ga))
#define CP_COMMIT()  asm volatile("cp.async.commit_group;")
#define CP_WAIT1()   asm volatile("cp.async.wait_group 1;")
#define CP_WAIT0()   asm volatile("cp.async.wait_group 0;")

__device__ __forceinline__ void mma8(float* c, const uint32_t* a, const uint32_t* b) {
    asm volatile(
        "mma.sync.aligned.m16n8k8.row.col.f32.tf32.tf32.f32 "
        "{%0,%1,%2,%3}, {%4,%5,%6,%7}, {%8,%9}, {%0,%1,%2,%3};\n"
        : "+f"(c[0]), "+f"(c[1]), "+f"(c[2]), "+f"(c[3])
        : "r"(a[0]), "r"(a[1]), "r"(a[2]), "r"(a[3]), "r"(b[0]), "r"(b[1]));
}

// ---------------------------------------------------------------------------
// Kernel 1: single-pass tf32 mma.sync GEMM, cp.async producer.
//   pre[1024,16384] = x[1024,9216] @ W_enc[9216,16384] + b_enc
// Warp tile 64x64 (vs 64x32 in R8): LDS per MMA drops 1.5 -> 1.0, smem
// crossbar load halves relative to the tensor window. Canonical m16n8k8
// fragment indexing identical to the R8 (passing) consumer.
// ---------------------------------------------------------------------------
__global__ __launch_bounds__(256, 1)
void enc_gemm(const float* __restrict__ A,
              const float* __restrict__ B,
              const float* __restrict__ bias)
{
    extern __shared__ float sm[];
    const uint32_t sbase = smem_u32(sm);

    const int tid  = threadIdx.x;
    const int wid  = tid >> 5;
    const int lane = tid & 31;
    const int by   = blockIdx.x;   // M tile (0..7)   -- fast-varying for B reuse
    const int bx   = blockIdx.y;   // N tile (0..63)

    const int wm = wid >> 2;       // 0..1  (64-row half)
    const int wn = wid & 3;        // 0..3  (64-col slice)
    const int g  = lane >> 2;      // 0..7
    const int t  = lane & 3;       // 0..3

    // producer smem byte offsets (within a stage); 256 threads, 6 CP16 each
    // A: 2 tasks -> task = tid + i*256, row = task>>2, quad = task&3
    // B: 4 tasks -> task = tid + i*256, krow = task>>6, cg = task&63
    const float* gA = A + (size_t)by * 128 * KDIM;
    const float* gB = B + (size_t)bx * 256;

#define ISSUE(stage, c)                                                          \
    do {                                                                         \
        const uint32_t _sb = sbase + (uint32_t)(stage) * STAGE_B;                \
        const int _k0 = (c) * KCH;                                               \
        _Pragma("unroll")                                                        \
        for (int _i = 0; _i < 2; _i++) {                                         \
            const int _task = tid + _i * 256;                                    \
            const int _row = _task >> 2, _q = _task & 3;                         \
            CP16(_sb + (uint32_t)_row * (A_PITCH * 4) + (uint32_t)_q * 16,       \
                 gA + (size_t)_row * KDIM + _k0 + _q * 4);                       \
        }                                                                        \
        _Pragma("unroll")                                                        \
        for (int _i = 0; _i < 4; _i++) {                                         \
            const int _task = tid + _i * 256;                                    \
            const int _kr = _task >> 6, _cg = _task & 63;                        \
            CP16(_sb + (uint32_t)(A_ST_F * 4)                                    \
                     + (uint32_t)_kr * (B_PITCH * 4) + (uint32_t)_cg * 16,       \
                 gB + (size_t)(_k0 + _kr) * DSAE + _cg * 4);                     \
        }                                                                        \
        CP_COMMIT();                                                             \
    } while (0)

    float acc[4][8][4];
#pragma unroll
    for (int mt = 0; mt < 4; mt++)
#pragma unroll
        for (int nt = 0; nt < 8; nt++)
#pragma unroll
            for (int q = 0; q < 4; q++) acc[mt][nt][q] = 0.f;

    ISSUE(0, 0);
    ISSUE(1, 1);

    int st = 0;
    for (int c = 0; c < NCHUNK; c++) {
        CP_WAIT1();
        __syncthreads();

        if (c + 2 < NCHUNK) {
            int ns = st + 2; if (ns >= NSTAGE) ns -= NSTAGE;
            ISSUE(ns, c + 2);
        }

        const float* As = sm + (size_t)st * STAGE_F;
        const float* Bs = As + A_ST_F;
#pragma unroll
        for (int ks = 0; ks < 2; ks++) {
            uint32_t Af[4][4], Bf[8][2];
#pragma unroll
            for (int mt = 0; mt < 4; mt++) {
                // canonical m16n8k8 A fragment: k = t, t+4 ; rows g, g+8
                const int r0 = (wm * 64 + mt * 16 + g) * A_PITCH + ks * 8 + t;
                Af[mt][0] = TF32RND(__float_as_uint(As[r0]));
                Af[mt][1] = TF32RND(__float_as_uint(As[r0 + 8 * A_PITCH]));
                Af[mt][2] = TF32RND(__float_as_uint(As[r0 + 4]));
                Af[mt][3] = TF32RND(__float_as_uint(As[r0 + 8 * A_PITCH + 4]));
            }
#pragma unroll
            for (int nt = 0; nt < 8; nt++) {
                // canonical B fragment: k = t, t+4 ; col g
                const int cb = (ks * 8 + t) * B_PITCH + wn * 64 + nt * 8 + g;
                Bf[nt][0] = TF32RND(__float_as_uint(Bs[cb]));
                Bf[nt][1] = TF32RND(__float_as_uint(Bs[cb + 4 * B_PITCH]));
            }
#pragma unroll
            for (int mt = 0; mt < 4; mt++)
#pragma unroll
                for (int nt = 0; nt < 8; nt++)
                    mma8(acc[mt][nt], Af[mt], Bf[nt]);
        }

        if (++st >= NSTAGE) st = 0;
    }
    CP_WAIT0();

    // ---- epilogue: +bias, store to g_pre ----
#pragma unroll
    for (int nt = 0; nt < 8; nt++) {
        const int col = bx * 256 + wn * 64 + nt * 8 + 2 * t;
        const float b0 = bias[col], b1 = bias[col + 1];
#pragma unroll
        for (int mt = 0; mt < 4; mt++) {
            const size_t r0 = (size_t)(by * 128 + wm * 64 + mt * 16 + g) * DSAE + col;
            *(float2*)(g_pre + r0) =
                make_float2(acc[mt][nt][0] + b0, acc[mt][nt][1] + b1);
            *(float2*)(g_pre + r0 + (size_t)8 * DSAE) =
                make_float2(acc[mt][nt][2] + b0, acc[mt][nt][3] + b1);
        }
    }
}

// ---------------------------------------------------------------------------
// Kernel 2: per-row top-64 radix select on approx pre + certain/band split
// ---------------------------------------------------------------------------
__device__ __forceinline__ unsigned f2k(float f) {
    unsigned u = __float_as_uint(f);
    return (u & 0x80000000u) ? ~u : (u | 0x80000000u);
}
__device__ __forceinline__ float k2f(unsigned k) {
    unsigned u = (k & 0x80000000u) ? (k & 0x7fffffffu) : ~k;
    return __uint_as_float(u);
}

__global__ void topk_kernel(float* __restrict__ z_out)
{
    extern __shared__ unsigned skeys[];          // DSAE * 4 = 64 KB
    __shared__ unsigned hist[256];
    __shared__ int s_digit, s_take, s_cnt;

    const int b   = blockIdx.x;
    const int tid = threadIdx.x;
    const float* row = g_pre + (size_t)b * DSAE;

    for (int e = tid; e < DSAE; e += 256) skeys[e] = f2k(row[e]);
    if (tid == 0) { s_cnt = 0; g_bcnt[b] = 0; }
    __syncthreads();

    unsigned prefix = 0;
    int k_rem = KTOP;
#pragma unroll
    for (int r = 0; r < 4; r++) {
        const int shift = 24 - 8 * r;
        hist[tid] = 0;
        __syncthreads();
        for (int e = tid; e < DSAE; e += 256) {
            const unsigned key = skeys[e];
            if (r == 0 || (key >> (shift + 8)) == prefix)
                atomicAdd(&hist[(key >> shift) & 255u], 1u);
        }
        __syncthreads();
        if (tid == 0) {
            int c = 0, d;
            for (d = 255; d > 0; --d) {
                const int h = (int)hist[d];
                if (c + h >= k_rem) break;
                c += h;
            }
            s_digit = d;
            s_take  = k_rem - c;
        }
        __syncthreads();
        prefix = (prefix << 8) | (unsigned)s_digit;
        k_rem  = s_take;
        __syncthreads();
    }

    const float kv     = k2f(prefix);   // approx 64th-largest value
    const float hi_thr = kv + DELTA;
    const float lo_thr = kv - DELTA;

    for (int e = tid; e < DSAE; e += 256) {
        const float v = k2f(skeys[e]);
        if (v > hi_thr) {
            // certainly in exact top-64 (approx error << DELTA)
            const float zv = fmaxf(v, 0.f);
            z_out[(size_t)b * DSAE + e] = zv;
            const int p = atomicAdd(&s_cnt, 1);
            g_idx[b * KTOP + p] = e;
            g_val[b * KTOP + p] = zv;
        } else {
            z_out[(size_t)b * DSAE + e] = 0.f;   // band entries fixed up later
            if (v >= lo_thr) {
                const int q = atomicAdd(&g_bcnt[b], 1);
                if (q < MAXB) g_bidx[b][q] = e;
            }
        }
    }
    __syncthreads();
    if (tid == 0) g_scnt[b] = s_cnt;
}

// ---------------------------------------------------------------------------
// Kernel 3: exact rescoring of band candidates
// ---------------------------------------------------------------------------
__global__ __launch_bounds__(256)
void rescore_kernel(const float* __restrict__ x,
                    const float* __restrict__ W,
                    const float* __restrict__ bias)
{
    const int slot = blockIdx.x;
    const int b    = blockIdx.y;
    int cnt = g_bcnt[b];
    if (cnt > MAXB) cnt = MAXB;
    if (slot >= cnt) return;

    __shared__ float wsum[8];
    const int tid  = threadIdx.x;
    const int col  = g_bidx[b][slot];
    const float* xr = x + (size_t)b * KDIM;
    const float* wc = W + col;

    float s = 0.f;
#pragma unroll
    for (int i = 0; i < KDIM / 256; i++) {
        const int k = tid + i * 256;
        s = fmaf(xr[k], __ldg(&wc[(size_t)k * DSAE]), s);
    }
#pragma unroll
    for (int o = 16; o > 0; o >>= 1) s += __shfl_down_sync(0xffffffffu, s, o);
    if ((tid & 31) == 0) wsum[tid >> 5] = s;
    __syncthreads();
    if (tid == 0) {
        float tot = 0.f;
#pragma unroll
        for (int w = 0; w < 8; w++) tot += wsum[w];
        g_bval[b][slot] = tot + bias[col];
    }
}

// ---------------------------------------------------------------------------
// Kernel 4: fixup — rank band entries by exact score, fill remaining slots
// ---------------------------------------------------------------------------
__global__ __launch_bounds__(MAXB)
void fixup_kernel(float* __restrict__ z_out)
{
    __shared__ int   bi[MAXB];
    __shared__ float bv[MAXB];

    const int b   = blockIdx.x;
    const int tid = threadIdx.x;
    int cnt = g_bcnt[b];
    if (cnt > MAXB) cnt = MAXB;
    const int scnt = g_scnt[b];
    const int rem  = KTOP - scnt;

    if (tid < cnt) { bi[tid] = g_bidx[b][tid]; bv[tid] = g_bval[b][tid]; }
    __syncthreads();

    if (tid < cnt) {
        const int   mi = bi[tid];
        const float mv = bv[tid];
        int rank = 0;
        for (int j = 0; j < cnt; j++)
            rank += (bv[j] > mv) || (bv[j] == mv && bi[j] < mi);
        if (rank < rem) {
            const float zv = fmaxf(mv, 0.f);
            z_out[(size_t)b * DSAE + mi] = zv;
            const int pos = scnt + rank;
            g_idx[b * KTOP + pos] = mi;
            g_val[b * KTOP + pos] = zv;
        }
    }
}

// ---------------------------------------------------------------------------
// Kernel 5: sparse decode + basis combine + x_hat + loss
// ---------------------------------------------------------------------------
__global__ __launch_bounds__(256)
void decode_kernel(const float* __restrict__ x,
                   const float* __restrict__ Wb,
                   const float* __restrict__ alpha,
                   const float* __restrict__ b_dec,
                   float* __restrict__ xhat,
                   float* __restrict__ loss)
{
    __shared__ int   sidx[KTOP];
    __shared__ float sval[KTOP];
    __shared__ float salpha[TDIM * KBASIS];
    __shared__ float warpsum[8];

    const int b = blockIdx.x, tid = threadIdx.x;
    if (tid < KTOP)          { sidx[tid] = g_idx[b * KTOP + tid]; sval[tid] = g_val[b * KTOP + tid]; }
    if (tid < TDIM * KBASIS) { salpha[tid] = alpha[tid]; }
    __syncthreads();

    float acc[KBASIS][3];
#pragma unroll
    for (int k3 = 0; k3 < KBASIS; k3++)
#pragma unroll
        for (int dd = 0; dd < 3; dd++) acc[k3][dd] = 0.f;

    for (int j = 0; j < KTOP; j++) {
        const float v = sval[j];
        if (v == 0.f) continue;
        const int s = sidx[j];
        const float* wr = Wb + (size_t)s * DIN;
#pragma unroll
        for (int k3 = 0; k3 < KBASIS; k3++) {
            const float* w = wr + (size_t)k3 * DSAE * DIN;
#pragma unroll
            for (int dd = 0; dd < 3; dd++)
                acc[k3][dd] = fmaf(v, __ldg(&w[tid + dd * 256]), acc[k3][dd]);
        }
    }

    float lsum = 0.f;
#pragma unroll
    for (int t = 0; t < TDIM; t++) {
        const float a0 = salpha[t * KBASIS + 0];
        const float a1 = salpha[t * KBASIS + 1];
        const float a2 = salpha[t * KBASIS + 2];
#pragma unroll
        for (int dd = 0; dd < 3; dd++) {
            const int d = tid + dd * 256;
            const size_t off = ((size_t)b * TDIM + t) * DIN + d;
            const float xh = a0 * acc[0][dd] + a1 * acc[1][dd] + a2 * acc[2][dd]
                           + b_dec[t * DIN + d];
            xhat[off] = xh;
            const float diff = xh - x[off];
            lsum = fmaf(diff, diff, lsum);
        }
    }

#pragma unroll
    for (int o = 16; o > 0; o >>= 1) lsum += __shfl_down_sync(0xffffffffu, lsum, o);
    if ((tid & 31) == 0) warpsum[tid >> 5] = lsum;
    __syncthreads();
    if (tid == 0) {
        float s = 0.f;
#pragma unroll
        for (int w = 0; w < 8; w++) s += warpsum[w];
        atomicAdd(loss, s * (1.0f / (float)(BSZ * TDIM)));
    }
}

// ---------------------------------------------------------------------------
// kernel_launch: inputs = [x, W_enc, b_enc, W_base, alpha, b_dec, k]
// output (f32, concat): [recon_loss(1), x_hat(B*T*DIN), z(B*DSAE)]
// ---------------------------------------------------------------------------
extern "C" void kernel_launch(void* const* d_in, const int* in_sizes, int n_in,
                              void* d_out, int out_size)
{
    const float* x      = (const float*)d_in[0];
    const float* W_enc  = (const float*)d_in[1];
    const float* b_enc  = (const float*)d_in[2];
    const float* W_base = (const float*)d_in[3];
    const float* alpha  = (const float*)d_in[4];
    const float* b_dec  = (const float*)d_in[5];

    float* out  = (float*)d_out;
    float* loss = out;
    float* xhat = out + 1;
    float* z    = out + 1 + (size_t)BSZ * TDIM * DIN;

    cudaMemsetAsync(loss, 0, sizeof(float));

    cudaFuncSetAttribute(enc_gemm,
                         cudaFuncAttributeMaxDynamicSharedMemorySize, SMEM_B);
    dim3 gemm_grid(BSZ / 128, DSAE / 256);   // (8, 64): M fast-varying
    enc_gemm<<<gemm_grid, 256, SMEM_B>>>(x, W_enc, b_enc);

    cudaFuncSetAttribute(topk_kernel,
                         cudaFuncAttributeMaxDynamicSharedMemorySize,
                         DSAE * (int)sizeof(unsigned));
    topk_kernel<<<BSZ, 256, DSAE * sizeof(unsigned)>>>(z);

    rescore_kernel<<<dim3(MAXB, BSZ), 256>>>(x, W_enc, b_enc);
    fixup_kernel<<<BSZ, MAXB>>>(z);

    decode_kernel<<<BSZ, 256>>>(x, W_base, alpha, b_dec, xhat, loss);
}

// round 10
// speedup vs baseline: 1.1287x; 1.0843x over previous
#include <cuda_runtime.h>
#include <cstdint>

// Problem constants (fixed shapes per reference)
#define DIN    768
#define DSAE   16384
#define TDIM   12
#define KTOP   64
#define KBASIS 3
#define BSZ    1024
#define KDIM   9216

// GEMM tiling: CTA 128x256, 256 threads (8 warps, 2M x 4N, warp tile 64x64)
// KCH=32 (halved barrier count), 4 stages (prefetch distance 3 chunks).
#define KCH      32
#define NCHUNK   (KDIM / KCH)     // 288
#define NSTAGE   4
#define A_PITCH  36               // 36 mod 32 = 4 -> A frag hits all 32 banks
#define B_PITCH  264              // 264 mod 32 = 8 -> B frag conflict-free
#define A_ST_F   (128 * A_PITCH)  // 4608 floats
#define B_ST_F   (32 * B_PITCH)   // 8448 floats
#define STAGE_F  (A_ST_F + B_ST_F)         // 13056 floats
#define STAGE_B  (STAGE_F * 4)             // 52224 bytes
#define SMEM_B   (NSTAGE * STAGE_B)        // 208896 bytes (< 227KB cap)

// band half-width around approx 64th value (~40 sigma of tf32 RNA noise)
#define DELTA  0.03f
#define MAXB   64

// round fp32 bits to nearest tf32 (MMA truncates low 13 bits; +bit12 = RNA)
#define TF32RND(u) ((u) + 0x1000u)

// ---------------------------------------------------------------------------
// Device scratch
// ---------------------------------------------------------------------------
__device__ float g_pre[(size_t)BSZ * DSAE];      // 64 MB
__device__ int   g_idx[BSZ * KTOP];
__device__ float g_val[BSZ * KTOP];
__device__ int   g_scnt[BSZ];                    // certain count per row
__device__ int   g_bcnt[BSZ];                    // band count per row
__device__ int   g_bidx[BSZ][MAXB];              // band candidate indices
__device__ float g_bval[BSZ][MAXB];              // exact rescored values

// ---------------------------------------------------------------------------
// helpers
// ---------------------------------------------------------------------------
__device__ __forceinline__ uint32_t smem_u32(const void* p) {
    uint32_t a;
    asm("{ .reg .u64 t; cvta.to.shared.u64 t, %1; cvt.u32.u64 %0, t; }" : "=r"(a) : "l"(p));
    return a;
}

#define CP16(sa, ga) \
    asm volatile("cp.async.cg.shared.global [%0], [%1], 16;" :: "r"(sa), "l"(ga))
#define CP_COMMIT()  asm volatile("cp.async.commit_group;")
#define CP_WAIT2()   asm volatile("cp.async.wait_group 2;")
#define CP_WAIT0()   asm volatile("cp.async.wait_group 0;")

__device__ __forceinline__ void mma8(float* c, const uint32_t* a, const uint32_t* b) {
    asm volatile(
        "mma.sync.aligned.m16n8k8.row.col.f32.tf32.tf32.f32 "
        "{%0,%1,%2,%3}, {%4,%5,%6,%7}, {%8,%9}, {%0,%1,%2,%3};\n"
        : "+f"(c[0]), "+f"(c[1]), "+f"(c[2]), "+f"(c[3])
        : "r"(a[0]), "r"(a[1]), "r"(a[2]), "r"(a[3]), "r"(b[0]), "r"(b[1]));
}

// no-op kernel: pads the launch index so ncu's skip-5 window captures enc_gemm
__global__ void nop_kernel() {}

// ---------------------------------------------------------------------------
// Kernel 1: single-pass tf32 mma.sync GEMM, cp.async producer.
//   pre[1024,16384] = x[1024,9216] @ W_enc[9216,16384] + b_enc
// KCH=32 + 4 stages: halves per-chunk barrier events and gives prefetch
// distance 3 (~6K cycles) to cover DRAM/L2 latency that R5/R8/R9 exposed
// (~1500 dead cycles per chunk across all three designs).
// ---------------------------------------------------------------------------
__global__ __launch_bounds__(256, 1)
void enc_gemm(const float* __restrict__ A,
              const float* __restrict__ B,
              const float* __restrict__ bias)
{
    extern __shared__ float sm[];
    const uint32_t sbase = smem_u32(sm);

    const int tid  = threadIdx.x;
    const int wid  = tid >> 5;
    const int lane = tid & 31;
    const int by   = blockIdx.x;   // M tile (0..7)   -- fast-varying for B reuse
    const int bx   = blockIdx.y;   // N tile (0..63)

    const int wm = wid >> 2;       // 0..1  (64-row half)
    const int wn = wid & 3;        // 0..3  (64-col slice)
    const int g  = lane >> 2;      // 0..7
    const int t  = lane & 3;       // 0..3

    const float* gA = A + (size_t)by * 128 * KDIM;
    const float* gB = B + (size_t)bx * 256;

    // producer: A = 128 rows x 32 floats = 1024 CP16 tasks (4/thread)
    //           B = 32 krows x 256 cols  = 2048 CP16 tasks (8/thread)
#define ISSUE(stage, c)                                                          \
    do {                                                                         \
        const uint32_t _sb = sbase + (uint32_t)(stage) * STAGE_B;                \
        const int _k0 = (c) * KCH;                                               \
        _Pragma("unroll")                                                        \
        for (int _i = 0; _i < 4; _i++) {                                         \
            const int _task = tid + _i * 256;                                    \
            const int _row = _task >> 3, _q = _task & 7;                         \
            CP16(_sb + (uint32_t)_row * (A_PITCH * 4) + (uint32_t)_q * 16,       \
                 gA + (size_t)_row * KDIM + _k0 + _q * 4);                       \
        }                                                                        \
        _Pragma("unroll")                                                        \
        for (int _i = 0; _i < 8; _i++) {                                         \
            const int _task = tid + _i * 256;                                    \
            const int _kr = _task >> 6, _cg = _task & 63;                        \
            CP16(_sb + (uint32_t)(A_ST_F * 4)                                    \
                     + (uint32_t)_kr * (B_PITCH * 4) + (uint32_t)_cg * 16,       \
                 gB + (size_t)(_k0 + _kr) * DSAE + _cg * 4);                     \
        }                                                                        \
        CP_COMMIT();                                                             \
    } while (0)

    float acc[4][8][4];
#pragma unroll
    for (int mt = 0; mt < 4; mt++)
#pragma unroll
        for (int nt = 0; nt < 8; nt++)
#pragma unroll
            for (int q = 0; q < 4; q++) acc[mt][nt][q] = 0.f;

    ISSUE(0, 0);
    ISSUE(1, 1);
    ISSUE(2, 2);

    int st = 0;
    for (int c = 0; c < NCHUNK; c++) {
        CP_WAIT2();              // group for chunk c complete (2 still in flight)
        __syncthreads();

        if (c + 3 < NCHUNK) {
            int ns = st + 3; if (ns >= NSTAGE) ns -= NSTAGE;
            ISSUE(ns, c + 3);
        }

        const float* As = sm + (size_t)st * STAGE_F;
        const float* Bs = As + A_ST_F;
#pragma unroll
        for (int ks = 0; ks < 4; ks++) {
            uint32_t Af[4][4], Bf[8][2];
#pragma unroll
            for (int mt = 0; mt < 4; mt++) {
                // canonical m16n8k8 A fragment: k = t, t+4 ; rows g, g+8
                const int r0 = (wm * 64 + mt * 16 + g) * A_PITCH + ks * 8 + t;
                Af[mt][0] = TF32RND(__float_as_uint(As[r0]));
                Af[mt][1] = TF32RND(__float_as_uint(As[r0 + 8 * A_PITCH]));
                Af[mt][2] = TF32RND(__float_as_uint(As[r0 + 4]));
                Af[mt][3] = TF32RND(__float_as_uint(As[r0 + 8 * A_PITCH + 4]));
            }
#pragma unroll
            for (int nt = 0; nt < 8; nt++) {
                // canonical B fragment: k = t, t+4 ; col g
                const int cb = (ks * 8 + t) * B_PITCH + wn * 64 + nt * 8 + g;
                Bf[nt][0] = TF32RND(__float_as_uint(Bs[cb]));
                Bf[nt][1] = TF32RND(__float_as_uint(Bs[cb + 4 * B_PITCH]));
            }
#pragma unroll
            for (int mt = 0; mt < 4; mt++)
#pragma unroll
                for (int nt = 0; nt < 8; nt++)
                    mma8(acc[mt][nt], Af[mt], Bf[nt]);
        }

        if (++st >= NSTAGE) st = 0;
    }
    CP_WAIT0();

    // ---- epilogue: +bias, store to g_pre ----
#pragma unroll
    for (int nt = 0; nt < 8; nt++) {
        const int col = bx * 256 + wn * 64 + nt * 8 + 2 * t;
        const float b0 = bias[col], b1 = bias[col + 1];
#pragma unroll
        for (int mt = 0; mt < 4; mt++) {
            const size_t r0 = (size_t)(by * 128 + wm * 64 + mt * 16 + g) * DSAE + col;
            *(float2*)(g_pre + r0) =
                make_float2(acc[mt][nt][0] + b0, acc[mt][nt][1] + b1);
            *(float2*)(g_pre + r0 + (size_t)8 * DSAE) =
                make_float2(acc[mt][nt][2] + b0, acc[mt][nt][3] + b1);
        }
    }
}

// ---------------------------------------------------------------------------
// Kernel 2: per-row top-64 radix select on approx pre + certain/band split
// ---------------------------------------------------------------------------
__device__ __forceinline__ unsigned f2k(float f) {
    unsigned u = __float_as_uint(f);
    return (u & 0x80000000u) ? ~u : (u | 0x80000000u);
}
__device__ __forceinline__ float k2f(unsigned k) {
    unsigned u = (k & 0x80000000u) ? (k & 0x7fffffffu) : ~k;
    return __uint_as_float(u);
}

__global__ void topk_kernel(float* __restrict__ z_out)
{
    extern __shared__ unsigned skeys[];          // DSAE * 4 = 64 KB
    __shared__ unsigned hist[256];
    __shared__ int s_digit, s_take, s_cnt;

    const int b   = blockIdx.x;
    const int tid = threadIdx.x;
    const float* row = g_pre + (size_t)b * DSAE;

    for (int e = tid; e < DSAE; e += 256) skeys[e] = f2k(row[e]);
    if (tid == 0) { s_cnt = 0; g_bcnt[b] = 0; }
    __syncthreads();

    unsigned prefix = 0;
    int k_rem = KTOP;
#pragma unroll
    for (int r = 0; r < 4; r++) {
        const int shift = 24 - 8 * r;
        hist[tid] = 0;
        __syncthreads();
        for (int e = tid; e < DSAE; e += 256) {
            const unsigned key = skeys[e];
            if (r == 0 || (key >> (shift + 8)) == prefix)
                atomicAdd(&hist[(key >> shift) & 255u], 1u);
        }
        __syncthreads();
        if (tid == 0) {
            int c = 0, d;
            for (d = 255; d > 0; --d) {
                const int h = (int)hist[d];
                if (c + h >= k_rem) break;
                c += h;
            }
            s_digit = d;
            s_take  = k_rem - c;
        }
        __syncthreads();
        prefix = (prefix << 8) | (unsigned)s_digit;
        k_rem  = s_take;
        __syncthreads();
    }

    const float kv     = k2f(prefix);   // approx 64th-largest value
    const float hi_thr = kv + DELTA;
    const float lo_thr = kv - DELTA;

    for (int e = tid; e < DSAE; e += 256) {
        const float v = k2f(skeys[e]);
        if (v > hi_thr) {
            // certainly in exact top-64 (approx error << DELTA)
            const float zv = fmaxf(v, 0.f);
            z_out[(size_t)b * DSAE + e] = zv;
            const int p = atomicAdd(&s_cnt, 1);
            g_idx[b * KTOP + p] = e;
            g_val[b * KTOP + p] = zv;
        } else {
            z_out[(size_t)b * DSAE + e] = 0.f;   // band entries fixed up later
            if (v >= lo_thr) {
                const int q = atomicAdd(&g_bcnt[b], 1);
                if (q < MAXB) g_bidx[b][q] = e;
            }
        }
    }
    __syncthreads();
    if (tid == 0) g_scnt[b] = s_cnt;
}

// ---------------------------------------------------------------------------
// Kernel 3: exact rescoring of band candidates
// ---------------------------------------------------------------------------
__global__ __launch_bounds__(256)
void rescore_kernel(const float* __restrict__ x,
                    const float* __restrict__ W,
                    const float* __restrict__ bias)
{
    const int slot = blockIdx.x;
    const int b    = blockIdx.y;
    int cnt = g_bcnt[b];
    if (cnt > MAXB) cnt = MAXB;
    if (slot >= cnt) return;

    __shared__ float wsum[8];
    const int tid  = threadIdx.x;
    const int col  = g_bidx[b][slot];
    const float* xr = x + (size_t)b * KDIM;
    const float* wc = W + col;

    float s = 0.f;
#pragma unroll
    for (int i = 0; i < KDIM / 256; i++) {
        const int k = tid + i * 256;
        s = fmaf(xr[k], __ldg(&wc[(size_t)k * DSAE]), s);
    }
#pragma unroll
    for (int o = 16; o > 0; o >>= 1) s += __shfl_down_sync(0xffffffffu, s, o);
    if ((tid & 31) == 0) wsum[tid >> 5] = s;
    __syncthreads();
    if (tid == 0) {
        float tot = 0.f;
#pragma unroll
        for (int w = 0; w < 8; w++) tot += wsum[w];
        g_bval[b][slot] = tot + bias[col];
    }
}

// ---------------------------------------------------------------------------
// Kernel 4: fixup — rank band entries by exact score, fill remaining slots
// ---------------------------------------------------------------------------
__global__ __launch_bounds__(MAXB)
void fixup_kernel(float* __restrict__ z_out)
{
    __shared__ int   bi[MAXB];
    __shared__ float bv[MAXB];

    const int b   = blockIdx.x;
    const int tid = threadIdx.x;
    int cnt = g_bcnt[b];
    if (cnt > MAXB) cnt = MAXB;
    const int scnt = g_scnt[b];
    const int rem  = KTOP - scnt;

    if (tid < cnt) { bi[tid] = g_bidx[b][tid]; bv[tid] = g_bval[b][tid]; }
    __syncthreads();

    if (tid < cnt) {
        const int   mi = bi[tid];
        const float mv = bv[tid];
        int rank = 0;
        for (int j = 0; j < cnt; j++)
            rank += (bv[j] > mv) || (bv[j] == mv && bi[j] < mi);
        if (rank < rem) {
            const float zv = fmaxf(mv, 0.f);
            z_out[(size_t)b * DSAE + mi] = zv;
            const int pos = scnt + rank;
            g_idx[b * KTOP + pos] = mi;
            g_val[b * KTOP + pos] = zv;
        }
    }
}

// ---------------------------------------------------------------------------
// Kernel 5: sparse decode + basis combine + x_hat + loss
// ---------------------------------------------------------------------------
__global__ __launch_bounds__(256)
void decode_kernel(const float* __restrict__ x,
                   const float* __restrict__ Wb,
                   const float* __restrict__ alpha,
                   const float* __restrict__ b_dec,
                   float* __restrict__ xhat,
                   float* __restrict__ loss)
{
    __shared__ int   sidx[KTOP];
    __shared__ float sval[KTOP];
    __shared__ float salpha[TDIM * KBASIS];
    __shared__ float warpsum[8];

    const int b = blockIdx.x, tid = threadIdx.x;
    if (tid < KTOP)          { sidx[tid] = g_idx[b * KTOP + tid]; sval[tid] = g_val[b * KTOP + tid]; }
    if (tid < TDIM * KBASIS) { salpha[tid] = alpha[tid]; }
    __syncthreads();

    float acc[KBASIS][3];
#pragma unroll
    for (int k3 = 0; k3 < KBASIS; k3++)
#pragma unroll
        for (int dd = 0; dd < 3; dd++) acc[k3][dd] = 0.f;

    for (int j = 0; j < KTOP; j++) {
        const float v = sval[j];
        if (v == 0.f) continue;
        const int s = sidx[j];
        const float* wr = Wb + (size_t)s * DIN;
#pragma unroll
        for (int k3 = 0; k3 < KBASIS; k3++) {
            const float* w = wr + (size_t)k3 * DSAE * DIN;
#pragma unroll
            for (int dd = 0; dd < 3; dd++)
                acc[k3][dd] = fmaf(v, __ldg(&w[tid + dd * 256]), acc[k3][dd]);
        }
    }

    float lsum = 0.f;
#pragma unroll
    for (int t = 0; t < TDIM; t++) {
        const float a0 = salpha[t * KBASIS + 0];
        const float a1 = salpha[t * KBASIS + 1];
        const float a2 = salpha[t * KBASIS + 2];
#pragma unroll
        for (int dd = 0; dd < 3; dd++) {
            const int d = tid + dd * 256;
            const size_t off = ((size_t)b * TDIM + t) * DIN + d;
            const float xh = a0 * acc[0][dd] + a1 * acc[1][dd] + a2 * acc[2][dd]
                           + b_dec[t * DIN + d];
            xhat[off] = xh;
            const float diff = xh - x[off];
            lsum = fmaf(diff, diff, lsum);
        }
    }

#pragma unroll
    for (int o = 16; o > 0; o >>= 1) lsum += __shfl_down_sync(0xffffffffu, lsum, o);
    if ((tid & 31) == 0) warpsum[tid >> 5] = lsum;
    __syncthreads();
    if (tid == 0) {
        float s = 0.f;
#pragma unroll
        for (int w = 0; w < 8; w++) s += warpsum[w];
        atomicAdd(loss, s * (1.0f / (float)(BSZ * TDIM)));
    }
}

// ---------------------------------------------------------------------------
// kernel_launch: inputs = [x, W_enc, b_enc, W_base, alpha, b_dec, k]
// output (f32, concat): [recon_loss(1), x_hat(B*T*DIN), z(B*DSAE)]
// ---------------------------------------------------------------------------
extern "C" void kernel_launch(void* const* d_in, const int* in_sizes, int n_in,
                              void* d_out, int out_size)
{
    const float* x      = (const float*)d_in[0];
    const float* W_enc  = (const float*)d_in[1];
    const float* b_enc  = (const float*)d_in[2];
    const float* W_base = (const float*)d_in[3];
    const float* alpha  = (const float*)d_in[4];
    const float* b_dec  = (const float*)d_in[5];

    float* out  = (float*)d_out;
    float* loss = out;
    float* xhat = out + 1;
    float* z    = out + 1 + (size_t)BSZ * TDIM * DIN;

    cudaMemsetAsync(loss, 0, sizeof(float));

    // pad launch count so ncu's skip-5 capture window lands on enc_gemm
    nop_kernel<<<1, 1>>>();
    nop_kernel<<<1, 1>>>();
    nop_kernel<<<1, 1>>>();
    nop_kernel<<<1, 1>>>();

    cudaFuncSetAttribute(enc_gemm,
                         cudaFuncAttributeMaxDynamicSharedMemorySize, SMEM_B);
    dim3 gemm_grid(BSZ / 128, DSAE / 256);   // (8, 64): M fast-varying
    enc_gemm<<<gemm_grid, 256, SMEM_B>>>(x, W_enc, b_enc);

    cudaFuncSetAttribute(topk_kernel,
                         cudaFuncAttributeMaxDynamicSharedMemorySize,
                         DSAE * (int)sizeof(unsigned));
    topk_kernel<<<BSZ, 256, DSAE * sizeof(unsigned)>>>(z);

    rescore_kernel<<<dim3(MAXB, BSZ), 256>>>(x, W_enc, b_enc);
    fixup_kernel<<<BSZ, MAXB>>>(z);

    decode_kernel<<<BSZ, 256>>>(x, W_base, alpha, b_dec, xhat, loss);
}

// round 11
// speedup vs baseline: 1.2092x; 1.0713x over previous
#include <cuda_runtime.h>
#include <cstdint>

// Problem constants (fixed shapes per reference)
#define DIN    768
#define DSAE   16384
#define TDIM   12
#define KTOP   64
#define KBASIS 3
#define BSZ    1024
#define KDIM   9216

// GEMM tiling: CTA 128x256, 256 threads (8 warps, 2M x 4N, warp tile 64x64)
// Split-K=2: each CTA covers K half (4608) -> 1024 CTAs -> 7 waves (1.2% waste
// vs 15% at 512 CTAs / 4 waves). Partials summed (+bias) inside topk.
#define KHALF    (KDIM / 2)       // 4608
#define KCH      32
#define NCHUNK   (KHALF / KCH)    // 144
#define NSTAGE   4
#define A_PITCH  36               // 36 mod 32 = 4 -> A frag hits all 32 banks
#define B_PITCH  264              // 264 mod 32 = 8 -> B frag conflict-free
#define A_ST_F   (128 * A_PITCH)  // 4608 floats
#define B_ST_F   (32 * B_PITCH)   // 8448 floats
#define STAGE_F  (A_ST_F + B_ST_F)         // 13056 floats
#define STAGE_B  (STAGE_F * 4)             // 52224 bytes
#define SMEM_B   (NSTAGE * STAGE_B)        // 208896 bytes (< 227KB cap)

// band half-width around approx 64th value (~40 sigma of tf32 RNA noise)
#define DELTA  0.03f
#define MAXB   64

// round fp32 bits to nearest tf32 (MMA truncates low 13 bits; +bit12 = RNA)
#define TF32RND(u) ((u) + 0x1000u)

// ---------------------------------------------------------------------------
// Device scratch
// ---------------------------------------------------------------------------
__device__ float g_pre [(size_t)BSZ * DSAE];     // 64 MB: K-half 0 partial
__device__ float g_pre2[(size_t)BSZ * DSAE];     // 64 MB: K-half 1 partial
__device__ int   g_idx[BSZ * KTOP];
__device__ float g_val[BSZ * KTOP];
__device__ int   g_scnt[BSZ];                    // certain count per row
__device__ int   g_bcnt[BSZ];                    // band count per row
__device__ int   g_bidx[BSZ][MAXB];              // band candidate indices
__device__ float g_bval[BSZ][MAXB];              // exact rescored values

// ---------------------------------------------------------------------------
// helpers
// ---------------------------------------------------------------------------
__device__ __forceinline__ uint32_t smem_u32(const void* p) {
    uint32_t a;
    asm("{ .reg .u64 t; cvta.to.shared.u64 t, %1; cvt.u32.u64 %0, t; }" : "=r"(a) : "l"(p));
    return a;
}

#define CP16(sa, ga) \
    asm volatile("cp.async.cg.shared.global [%0], [%1], 16;" :: "r"(sa), "l"(ga))
#define CP_COMMIT()  asm volatile("cp.async.commit_group;")
#define CP_WAIT2()   asm volatile("cp.async.wait_group 2;")
#define CP_WAIT0()   asm volatile("cp.async.wait_group 0;")

__device__ __forceinline__ void mma8(float* c, const uint32_t* a, const uint32_t* b) {
    asm volatile(
        "mma.sync.aligned.m16n8k8.row.col.f32.tf32.tf32.f32 "
        "{%0,%1,%2,%3}, {%4,%5,%6,%7}, {%8,%9}, {%0,%1,%2,%3};\n"
        : "+f"(c[0]), "+f"(c[1]), "+f"(c[2]), "+f"(c[3])
        : "r"(a[0]), "r"(a[1]), "r"(a[2]), "r"(a[3]), "r"(b[0]), "r"(b[1]));
}

// no-op kernel: pads launch index so ncu (-s 5) lands on enc_gemm.
// Index map: harness d_out poison = 0, our memset = 1, nops = 2..4, gemm = 5.
__global__ void nop_kernel() {}

// ---------------------------------------------------------------------------
// Kernel 1: single-pass tf32 mma.sync GEMM, cp.async producer, split-K=2.
//   partial[1024,16384] = x[:, kz*4608:(kz+1)*4608] @ W_enc[kz half]
// (bias and half-sum folded into topk)
// ---------------------------------------------------------------------------
__global__ __launch_bounds__(256, 1)
void enc_gemm(const float* __restrict__ A,
              const float* __restrict__ B)
{
    extern __shared__ float sm[];
    const uint32_t sbase = smem_u32(sm);

    const int tid  = threadIdx.x;
    const int wid  = tid >> 5;
    const int lane = tid & 31;
    const int by   = blockIdx.x;   // M tile (0..7)   -- fast-varying for B reuse
    const int bx   = blockIdx.y;   // N tile (0..63)
    const int kz   = blockIdx.z;   // K half (0..1)

    const int wm = wid >> 2;       // 0..1  (64-row half)
    const int wn = wid & 3;        // 0..3  (64-col slice)
    const int g  = lane >> 2;      // 0..7
    const int t  = lane & 3;       // 0..3

    const float* gA = A + (size_t)by * 128 * KDIM + (size_t)kz * KHALF;
    const float* gB = B + (size_t)kz * KHALF * DSAE + (size_t)bx * 256;
    float* gOut = (kz == 0 ? g_pre : g_pre2);

    // producer: A = 128 rows x 32 floats = 1024 CP16 tasks (4/thread)
    //           B = 32 krows x 256 cols  = 2048 CP16 tasks (8/thread)
#define ISSUE(stage, c)                                                          \
    do {                                                                         \
        const uint32_t _sb = sbase + (uint32_t)(stage) * STAGE_B;                \
        const int _k0 = (c) * KCH;                                               \
        _Pragma("unroll")                                                        \
        for (int _i = 0; _i < 4; _i++) {                                         \
            const int _task = tid + _i * 256;                                    \
            const int _row = _task >> 3, _q = _task & 7;                         \
            CP16(_sb + (uint32_t)_row * (A_PITCH * 4) + (uint32_t)_q * 16,       \
                 gA + (size_t)_row * KDIM + _k0 + _q * 4);                       \
        }                                                                        \
        _Pragma("unroll")                                                        \
        for (int _i = 0; _i < 8; _i++) {                                         \
            const int _task = tid + _i * 256;                                    \
            const int _kr = _task >> 6, _cg = _task & 63;                        \
            CP16(_sb + (uint32_t)(A_ST_F * 4)                                    \
                     + (uint32_t)_kr * (B_PITCH * 4) + (uint32_t)_cg * 16,       \
                 gB + (size_t)(_k0 + _kr) * DSAE + _cg * 4);                     \
        }                                                                        \
        CP_COMMIT();                                                             \
    } while (0)

    float acc[4][8][4];
#pragma unroll
    for (int mt = 0; mt < 4; mt++)
#pragma unroll
        for (int nt = 0; nt < 8; nt++)
#pragma unroll
            for (int q = 0; q < 4; q++) acc[mt][nt][q] = 0.f;

    ISSUE(0, 0);
    ISSUE(1, 1);
    ISSUE(2, 2);

    int st = 0;
    for (int c = 0; c < NCHUNK; c++) {
        CP_WAIT2();              // group for chunk c complete (2 still in flight)
        __syncthreads();

        if (c + 3 < NCHUNK) {
            int ns = st + 3; if (ns >= NSTAGE) ns -= NSTAGE;
            ISSUE(ns, c + 3);
        }

        const float* As = sm + (size_t)st * STAGE_F;
        const float* Bs = As + A_ST_F;
#pragma unroll
        for (int ks = 0; ks < 4; ks++) {
            uint32_t Af[4][4], Bf[8][2];
#pragma unroll
            for (int mt = 0; mt < 4; mt++) {
                // canonical m16n8k8 A fragment: k = t, t+4 ; rows g, g+8
                const int r0 = (wm * 64 + mt * 16 + g) * A_PITCH + ks * 8 + t;
                Af[mt][0] = TF32RND(__float_as_uint(As[r0]));
                Af[mt][1] = TF32RND(__float_as_uint(As[r0 + 8 * A_PITCH]));
                Af[mt][2] = TF32RND(__float_as_uint(As[r0 + 4]));
                Af[mt][3] = TF32RND(__float_as_uint(As[r0 + 8 * A_PITCH + 4]));
            }
#pragma unroll
            for (int nt = 0; nt < 8; nt++) {
                // canonical B fragment: k = t, t+4 ; col g
                const int cb = (ks * 8 + t) * B_PITCH + wn * 64 + nt * 8 + g;
                Bf[nt][0] = TF32RND(__float_as_uint(Bs[cb]));
                Bf[nt][1] = TF32RND(__float_as_uint(Bs[cb + 4 * B_PITCH]));
            }
#pragma unroll
            for (int mt = 0; mt < 4; mt++)
#pragma unroll
                for (int nt = 0; nt < 8; nt++)
                    mma8(acc[mt][nt], Af[mt], Bf[nt]);
        }

        if (++st >= NSTAGE) st = 0;
    }
    CP_WAIT0();

    // ---- epilogue: store raw partial (bias + half-sum folded into topk) ----
#pragma unroll
    for (int nt = 0; nt < 8; nt++) {
        const int col = bx * 256 + wn * 64 + nt * 8 + 2 * t;
#pragma unroll
        for (int mt = 0; mt < 4; mt++) {
            const size_t r0 = (size_t)(by * 128 + wm * 64 + mt * 16 + g) * DSAE + col;
            *(float2*)(gOut + r0) =
                make_float2(acc[mt][nt][0], acc[mt][nt][1]);
            *(float2*)(gOut + r0 + (size_t)8 * DSAE) =
                make_float2(acc[mt][nt][2], acc[mt][nt][3]);
        }
    }
}

// ---------------------------------------------------------------------------
// Kernel 2: per-row top-64 radix select on approx pre + certain/band split.
// pre = g_pre + g_pre2 + bias computed on load (split-K reduction fused here).
// ---------------------------------------------------------------------------
__device__ __forceinline__ unsigned f2k(float f) {
    unsigned u = __float_as_uint(f);
    return (u & 0x80000000u) ? ~u : (u | 0x80000000u);
}
__device__ __forceinline__ float k2f(unsigned k) {
    unsigned u = (k & 0x80000000u) ? (k & 0x7fffffffu) : ~k;
    return __uint_as_float(u);
}

__global__ void topk_kernel(float* __restrict__ z_out,
                            const float* __restrict__ bias)
{
    extern __shared__ unsigned skeys[];          // DSAE * 4 = 64 KB
    __shared__ unsigned hist[256];
    __shared__ int s_digit, s_take, s_cnt;

    const int b   = blockIdx.x;
    const int tid = threadIdx.x;
    const float* p0 = g_pre  + (size_t)b * DSAE;
    const float* p1 = g_pre2 + (size_t)b * DSAE;

    for (int e = tid; e < DSAE; e += 256)
        skeys[e] = f2k(p0[e] + p1[e] + bias[e]);
    if (tid == 0) { s_cnt = 0; g_bcnt[b] = 0; }
    __syncthreads();

    unsigned prefix = 0;
    int k_rem = KTOP;
#pragma unroll
    for (int r = 0; r < 4; r++) {
        const int shift = 24 - 8 * r;
        hist[tid] = 0;
        __syncthreads();
        for (int e = tid; e < DSAE; e += 256) {
            const unsigned key = skeys[e];
            if (r == 0 || (key >> (shift + 8)) == prefix)
                atomicAdd(&hist[(key >> shift) & 255u], 1u);
        }
        __syncthreads();
        if (tid == 0) {
            int c = 0, d;
            for (d = 255; d > 0; --d) {
                const int h = (int)hist[d];
                if (c + h >= k_rem) break;
                c += h;
            }
            s_digit = d;
            s_take  = k_rem - c;
        }
        __syncthreads();
        prefix = (prefix << 8) | (unsigned)s_digit;
        k_rem  = s_take;
        __syncthreads();
    }

    const float kv     = k2f(prefix);   // approx 64th-largest value
    const float hi_thr = kv + DELTA;
    const float lo_thr = kv - DELTA;

    for (int e = tid; e < DSAE; e += 256) {
        const float v = k2f(skeys[e]);
        if (v > hi_thr) {
            // certainly in exact top-64 (approx error << DELTA)
            const float zv = fmaxf(v, 0.f);
            z_out[(size_t)b * DSAE + e] = zv;
            const int p = atomicAdd(&s_cnt, 1);
            g_idx[b * KTOP + p] = e;
            g_val[b * KTOP + p] = zv;
        } else {
            z_out[(size_t)b * DSAE + e] = 0.f;   // band entries fixed up later
            if (v >= lo_thr) {
                const int q = atomicAdd(&g_bcnt[b], 1);
                if (q < MAXB) g_bidx[b][q] = e;
            }
        }
    }
    __syncthreads();
    if (tid == 0) g_scnt[b] = s_cnt;
}

// ---------------------------------------------------------------------------
// Kernel 3: exact rescoring of band candidates
// ---------------------------------------------------------------------------
__global__ __launch_bounds__(256)
void rescore_kernel(const float* __restrict__ x,
                    const float* __restrict__ W,
                    const float* __restrict__ bias)
{
    const int slot = blockIdx.x;
    const int b    = blockIdx.y;
    int cnt = g_bcnt[b];
    if (cnt > MAXB) cnt = MAXB;
    if (slot >= cnt) return;

    __shared__ float wsum[8];
    const int tid  = threadIdx.x;
    const int col  = g_bidx[b][slot];
    const float* xr = x + (size_t)b * KDIM;
    const float* wc = W + col;

    float s = 0.f;
#pragma unroll
    for (int i = 0; i < KDIM / 256; i++) {
        const int k = tid + i * 256;
        s = fmaf(xr[k], __ldg(&wc[(size_t)k * DSAE]), s);
    }
#pragma unroll
    for (int o = 16; o > 0; o >>= 1) s += __shfl_down_sync(0xffffffffu, s, o);
    if ((tid & 31) == 0) wsum[tid >> 5] = s;
    __syncthreads();
    if (tid == 0) {
        float tot = 0.f;
#pragma unroll
        for (int w = 0; w < 8; w++) tot += wsum[w];
        g_bval[b][slot] = tot + bias[col];
    }
}

// ---------------------------------------------------------------------------
// Kernel 4: fixup — rank band entries by exact score, fill remaining slots
// ---------------------------------------------------------------------------
__global__ __launch_bounds__(MAXB)
void fixup_kernel(float* __restrict__ z_out)
{
    __shared__ int   bi[MAXB];
    __shared__ float bv[MAXB];

    const int b   = blockIdx.x;
    const int tid = threadIdx.x;
    int cnt = g_bcnt[b];
    if (cnt > MAXB) cnt = MAXB;
    const int scnt = g_scnt[b];
    const int rem  = KTOP - scnt;

    if (tid < cnt) { bi[tid] = g_bidx[b][tid]; bv[tid] = g_bval[b][tid]; }
    __syncthreads();

    if (tid < cnt) {
        const int   mi = bi[tid];
        const float mv = bv[tid];
        int rank = 0;
        for (int j = 0; j < cnt; j++)
            rank += (bv[j] > mv) || (bv[j] == mv && bi[j] < mi);
        if (rank < rem) {
            const float zv = fmaxf(mv, 0.f);
            z_out[(size_t)b * DSAE + mi] = zv;
            const int pos = scnt + rank;
            g_idx[b * KTOP + pos] = mi;
            g_val[b * KTOP + pos] = zv;
        }
    }
}

// ---------------------------------------------------------------------------
// Kernel 5: sparse decode + basis combine + x_hat + loss
// ---------------------------------------------------------------------------
__global__ __launch_bounds__(256)
void decode_kernel(const float* __restrict__ x,
                   const float* __restrict__ Wb,
                   const float* __restrict__ alpha,
                   const float* __restrict__ b_dec,
                   float* __restrict__ xhat,
                   float* __restrict__ loss)
{
    __shared__ int   sidx[KTOP];
    __shared__ float sval[KTOP];
    __shared__ float salpha[TDIM * KBASIS];
    __shared__ float warpsum[8];

    const int b = blockIdx.x, tid = threadIdx.x;
    if (tid < KTOP)          { sidx[tid] = g_idx[b * KTOP + tid]; sval[tid] = g_val[b * KTOP + tid]; }
    if (tid < TDIM * KBASIS) { salpha[tid] = alpha[tid]; }
    __syncthreads();

    float acc[KBASIS][3];
#pragma unroll
    for (int k3 = 0; k3 < KBASIS; k3++)
#pragma unroll
        for (int dd = 0; dd < 3; dd++) acc[k3][dd] = 0.f;

    for (int j = 0; j < KTOP; j++) {
        const float v = sval[j];
        if (v == 0.f) continue;
        const int s = sidx[j];
        const float* wr = Wb + (size_t)s * DIN;
#pragma unroll
        for (int k3 = 0; k3 < KBASIS; k3++) {
            const float* w = wr + (size_t)k3 * DSAE * DIN;
#pragma unroll
            for (int dd = 0; dd < 3; dd++)
                acc[k3][dd] = fmaf(v, __ldg(&w[tid + dd * 256]), acc[k3][dd]);
        }
    }

    float lsum = 0.f;
#pragma unroll
    for (int t = 0; t < TDIM; t++) {
        const float a0 = salpha[t * KBASIS + 0];
        const float a1 = salpha[t * KBASIS + 1];
        const float a2 = salpha[t * KBASIS + 2];
#pragma unroll
        for (int dd = 0; dd < 3; dd++) {
            const int d = tid + dd * 256;
            const size_t off = ((size_t)b * TDIM + t) * DIN + d;
            const float xh = a0 * acc[0][dd] + a1 * acc[1][dd] + a2 * acc[2][dd]
                           + b_dec[t * DIN + d];
            xhat[off] = xh;
            const float diff = xh - x[off];
            lsum = fmaf(diff, diff, lsum);
        }
    }

#pragma unroll
    for (int o = 16; o > 0; o >>= 1) lsum += __shfl_down_sync(0xffffffffu, lsum, o);
    if ((tid & 31) == 0) warpsum[tid >> 5] = lsum;
    __syncthreads();
    if (tid == 0) {
        float s = 0.f;
#pragma unroll
        for (int w = 0; w < 8; w++) s += warpsum[w];
        atomicAdd(loss, s * (1.0f / (float)(BSZ * TDIM)));
    }
}

// ---------------------------------------------------------------------------
// kernel_launch: inputs = [x, W_enc, b_enc, W_base, alpha, b_dec, k]
// output (f32, concat): [recon_loss(1), x_hat(B*T*DIN), z(B*DSAE)]
// ---------------------------------------------------------------------------
extern "C" void kernel_launch(void* const* d_in, const int* in_sizes, int n_in,
                              void* d_out, int out_size)
{
    const float* x      = (const float*)d_in[0];
    const float* W_enc  = (const float*)d_in[1];
    const float* b_enc  = (const float*)d_in[2];
    const float* W_base = (const float*)d_in[3];
    const float* alpha  = (const float*)d_in[4];
    const float* b_dec  = (const float*)d_in[5];

    float* out  = (float*)d_out;
    float* loss = out;
    float* xhat = out + 1;
    float* z    = out + 1 + (size_t)BSZ * TDIM * DIN;

    cudaMemsetAsync(loss, 0, sizeof(float));

    // pad launch count: harness poison=0, memset=1, nops=2..4 -> gemm at 5
    nop_kernel<<<1, 1>>>();
    nop_kernel<<<1, 1>>>();
    nop_kernel<<<1, 1>>>();

    cudaFuncSetAttribute(enc_gemm,
                         cudaFuncAttributeMaxDynamicSharedMemorySize, SMEM_B);
    dim3 gemm_grid(BSZ / 128, DSAE / 256, 2);   // (8, 64, 2): split-K
    enc_gemm<<<gemm_grid, 256, SMEM_B>>>(x, W_enc);

    cudaFuncSetAttribute(topk_kernel,
                         cudaFuncAttributeMaxDynamicSharedMemorySize,
                         DSAE * (int)sizeof(unsigned));
    topk_kernel<<<BSZ, 256, DSAE * sizeof(unsigned)>>>(z, b_enc);

    rescore_kernel<<<dim3(MAXB, BSZ), 256>>>(x, W_enc, b_enc);
    fixup_kernel<<<BSZ, MAXB>>>(z);

    decode_kernel<<<BSZ, 256>>>(x, W_base, alpha, b_dec, xhat, loss);
}

// round 12
// speedup vs baseline: 1.2381x; 1.0238x over previous
#include <cuda_runtime.h>
#include <cstdint>

// Problem constants (fixed shapes per reference)
#define DIN    768
#define DSAE   16384
#define TDIM   12
#define KTOP   64
#define KBASIS 3
#define BSZ    1024
#define KDIM   9216

// GEMM tiling: CTA 128x128, 128 threads (4 warps, 2M x 2N, warp tile 64x64),
// 2 CTAs/SM so chunk-boundary bubbles of one CTA overlap the other's MMAs.
// Split-K=2 -> grid (8,128,2) = 2048 CTAs / 296 slots = 6.92 waves.
#define KHALF    (KDIM / 2)       // 4608
#define KCH      32
#define NCHUNK   (KHALF / KCH)    // 144
#define NSTAGE   3
#define A_PITCH  36               // 36 mod 32 = 4 -> A frag hits all 32 banks
#define B_PITCH  136              // 136 mod 32 = 8 -> B frag conflict-free
#define A_ST_F   (128 * A_PITCH)  // 4608 floats
#define B_ST_F   (32 * B_PITCH)   // 4352 floats
#define STAGE_F  (A_ST_F + B_ST_F)         // 8960 floats
#define STAGE_B  (STAGE_F * 4)             // 35840 bytes
#define SMEM_B   (NSTAGE * STAGE_B)        // 107520 bytes (x2 CTAs = 215KB/SM)

// band half-width around approx 64th value (~40 sigma of tf32 RNA noise)
#define DELTA  0.03f
#define MAXB   64

// round fp32 bits to nearest tf32 (MMA truncates low 13 bits; +bit12 = RNA)
#define TF32RND(u) ((u) + 0x1000u)

// ---------------------------------------------------------------------------
// Device scratch
// ---------------------------------------------------------------------------
__device__ float g_pre [(size_t)BSZ * DSAE];     // 64 MB: K-half 0 partial
__device__ float g_pre2[(size_t)BSZ * DSAE];     // 64 MB: K-half 1 partial
__device__ int   g_idx[BSZ * KTOP];
__device__ float g_val[BSZ * KTOP];
__device__ int   g_scnt[BSZ];                    // certain count per row
__device__ int   g_bcnt[BSZ];                    // band count per row
__device__ int   g_bidx[BSZ][MAXB];              // band candidate indices
__device__ float g_bval[BSZ][MAXB];              // exact rescored values

// ---------------------------------------------------------------------------
// helpers
// ---------------------------------------------------------------------------
__device__ __forceinline__ uint32_t smem_u32(const void* p) {
    uint32_t a;
    asm("{ .reg .u64 t; cvta.to.shared.u64 t, %1; cvt.u32.u64 %0, t; }" : "=r"(a) : "l"(p));
    return a;
}

#define CP16(sa, ga) \
    asm volatile("cp.async.cg.shared.global [%0], [%1], 16;" :: "r"(sa), "l"(ga))
#define CP_COMMIT()  asm volatile("cp.async.commit_group;")
#define CP_WAIT1()   asm volatile("cp.async.wait_group 1;")
#define CP_WAIT0()   asm volatile("cp.async.wait_group 0;")

__device__ __forceinline__ void mma8(float* c, const uint32_t* a, const uint32_t* b) {
    asm volatile(
        "mma.sync.aligned.m16n8k8.row.col.f32.tf32.tf32.f32 "
        "{%0,%1,%2,%3}, {%4,%5,%6,%7}, {%8,%9}, {%0,%1,%2,%3};\n"
        : "+f"(c[0]), "+f"(c[1]), "+f"(c[2]), "+f"(c[3])
        : "r"(a[0]), "r"(a[1]), "r"(a[2]), "r"(a[3]), "r"(b[0]), "r"(b[1]));
}

// no-op kernel: pads launch index so ncu (-s 5) lands on enc_gemm.
// Index map: harness d_out poison = 0, our memset = 1, nops = 2..4, gemm = 5.
__global__ void nop_kernel() {}

// ---------------------------------------------------------------------------
// Kernel 1: single-pass tf32 mma.sync GEMM, cp.async producer, split-K=2,
// 2 CTAs/SM (128 threads, 128x128 tile, warp tile 64x64).
//   partial[1024,16384] = x[:, kz*4608:(kz+1)*4608] @ W_enc[kz half]
// (bias and half-sum folded into topk)
// ---------------------------------------------------------------------------
__global__ __launch_bounds__(128, 2)
void enc_gemm(const float* __restrict__ A,
              const float* __restrict__ B)
{
    extern __shared__ float sm[];
    const uint32_t sbase = smem_u32(sm);

    const int tid  = threadIdx.x;
    const int wid  = tid >> 5;
    const int lane = tid & 31;
    const int by   = blockIdx.x;   // M tile (0..7)   -- fast-varying for B reuse
    const int bx   = blockIdx.y;   // N tile (0..127)
    const int kz   = blockIdx.z;   // K half (0..1)

    const int wm = wid >> 1;       // 0..1  (64-row half)
    const int wn = wid & 1;        // 0..1  (64-col half)
    const int g  = lane >> 2;      // 0..7
    const int t  = lane & 3;       // 0..3

    const float* gA = A + (size_t)by * 128 * KDIM + (size_t)kz * KHALF;
    const float* gB = B + (size_t)kz * KHALF * DSAE + (size_t)bx * 128;
    float* gOut = (kz == 0 ? g_pre : g_pre2);

    // producer (128 threads): A = 128 rows x 32 floats = 1024 CP16 (8/thread)
    //                         B = 32 krows x 128 cols  = 1024 CP16 (8/thread)
#define ISSUE(stage, c)                                                          \
    do {                                                                         \
        const uint32_t _sb = sbase + (uint32_t)(stage) * STAGE_B;                \
        const int _k0 = (c) * KCH;                                               \
        _Pragma("unroll")                                                        \
        for (int _i = 0; _i < 8; _i++) {                                         \
            const int _task = tid + _i * 128;                                    \
            const int _row = _task >> 3, _q = _task & 7;                         \
            CP16(_sb + (uint32_t)_row * (A_PITCH * 4) + (uint32_t)_q * 16,       \
                 gA + (size_t)_row * KDIM + _k0 + _q * 4);                       \
        }                                                                        \
        _Pragma("unroll")                                                        \
        for (int _i = 0; _i < 8; _i++) {                                         \
            const int _task = tid + _i * 128;                                    \
            const int _kr = _task >> 5, _cg = _task & 31;                        \
            CP16(_sb + (uint32_t)(A_ST_F * 4)                                    \
                     + (uint32_t)_kr * (B_PITCH * 4) + (uint32_t)_cg * 16,       \
                 gB + (size_t)(_k0 + _kr) * DSAE + _cg * 4);                     \
        }                                                                        \
        CP_COMMIT();                                                             \
    } while (0)

    float acc[4][8][4];
#pragma unroll
    for (int mt = 0; mt < 4; mt++)
#pragma unroll
        for (int nt = 0; nt < 8; nt++)
#pragma unroll
            for (int q = 0; q < 4; q++) acc[mt][nt][q] = 0.f;

    ISSUE(0, 0);
    ISSUE(1, 1);

    int st = 0;
    for (int c = 0; c < NCHUNK; c++) {
        CP_WAIT1();              // group for chunk c complete (1 still in flight)
        __syncthreads();

        if (c + 2 < NCHUNK) {
            int ns = st + 2; if (ns >= NSTAGE) ns -= NSTAGE;
            ISSUE(ns, c + 2);
        }

        const float* As = sm + (size_t)st * STAGE_F;
        const float* Bs = As + A_ST_F;
#pragma unroll
        for (int ks = 0; ks < 4; ks++) {
            uint32_t Af[4][4], Bf[8][2];
#pragma unroll
            for (int mt = 0; mt < 4; mt++) {
                // canonical m16n8k8 A fragment: k = t, t+4 ; rows g, g+8
                const int r0 = (wm * 64 + mt * 16 + g) * A_PITCH + ks * 8 + t;
                Af[mt][0] = TF32RND(__float_as_uint(As[r0]));
                Af[mt][1] = TF32RND(__float_as_uint(As[r0 + 8 * A_PITCH]));
                Af[mt][2] = TF32RND(__float_as_uint(As[r0 + 4]));
                Af[mt][3] = TF32RND(__float_as_uint(As[r0 + 8 * A_PITCH + 4]));
            }
#pragma unroll
            for (int nt = 0; nt < 8; nt++) {
                // canonical B fragment: k = t, t+4 ; col g
                const int cb = (ks * 8 + t) * B_PITCH + wn * 64 + nt * 8 + g;
                Bf[nt][0] = TF32RND(__float_as_uint(Bs[cb]));
                Bf[nt][1] = TF32RND(__float_as_uint(Bs[cb + 4 * B_PITCH]));
            }
#pragma unroll
            for (int mt = 0; mt < 4; mt++)
#pragma unroll
                for (int nt = 0; nt < 8; nt++)
                    mma8(acc[mt][nt], Af[mt], Bf[nt]);
        }

        if (++st >= NSTAGE) st = 0;
    }
    CP_WAIT0();

    // ---- epilogue: store raw partial (bias + half-sum folded into topk) ----
#pragma unroll
    for (int nt = 0; nt < 8; nt++) {
        const int col = bx * 128 + wn * 64 + nt * 8 + 2 * t;
#pragma unroll
        for (int mt = 0; mt < 4; mt++) {
            const size_t r0 = (size_t)(by * 128 + wm * 64 + mt * 16 + g) * DSAE + col;
            *(float2*)(gOut + r0) =
                make_float2(acc[mt][nt][0], acc[mt][nt][1]);
            *(float2*)(gOut + r0 + (size_t)8 * DSAE) =
                make_float2(acc[mt][nt][2], acc[mt][nt][3]);
        }
    }
}

// ---------------------------------------------------------------------------
// Kernel 2: per-row top-64 radix select on approx pre + certain/band split.
// pre = g_pre + g_pre2 + bias computed on load (split-K reduction fused here).
// ---------------------------------------------------------------------------
__device__ __forceinline__ unsigned f2k(float f) {
    unsigned u = __float_as_uint(f);
    return (u & 0x80000000u) ? ~u : (u | 0x80000000u);
}
__device__ __forceinline__ float k2f(unsigned k) {
    unsigned u = (k & 0x80000000u) ? (k & 0x7fffffffu) : ~k;
    return __uint_as_float(u);
}

__global__ void topk_kernel(float* __restrict__ z_out,
                            const float* __restrict__ bias)
{
    extern __shared__ unsigned skeys[];          // DSAE * 4 = 64 KB
    __shared__ unsigned hist[256];
    __shared__ int s_digit, s_take, s_cnt;

    const int b   = blockIdx.x;
    const int tid = threadIdx.x;
    const float* p0 = g_pre  + (size_t)b * DSAE;
    const float* p1 = g_pre2 + (size_t)b * DSAE;

    for (int e = tid; e < DSAE; e += 256)
        skeys[e] = f2k(p0[e] + p1[e] + bias[e]);
    if (tid == 0) { s_cnt = 0; g_bcnt[b] = 0; }
    __syncthreads();

    unsigned prefix = 0;
    int k_rem = KTOP;
#pragma unroll
    for (int r = 0; r < 4; r++) {
        const int shift = 24 - 8 * r;
        hist[tid] = 0;
        __syncthreads();
        for (int e = tid; e < DSAE; e += 256) {
            const unsigned key = skeys[e];
            if (r == 0 || (key >> (shift + 8)) == prefix)
                atomicAdd(&hist[(key >> shift) & 255u], 1u);
        }
        __syncthreads();
        if (tid == 0) {
            int c = 0, d;
            for (d = 255; d > 0; --d) {
                const int h = (int)hist[d];
                if (c + h >= k_rem) break;
                c += h;
            }
            s_digit = d;
            s_take  = k_rem - c;
        }
        __syncthreads();
        prefix = (prefix << 8) | (unsigned)s_digit;
        k_rem  = s_take;
        __syncthreads();
    }

    const float kv     = k2f(prefix);   // approx 64th-largest value
    const float hi_thr = kv + DELTA;
    const float lo_thr = kv - DELTA;

    for (int e = tid; e < DSAE; e += 256) {
        const float v = k2f(skeys[e]);
        if (v > hi_thr) {
            // certainly in exact top-64 (approx error << DELTA)
            const float zv = fmaxf(v, 0.f);
            z_out[(size_t)b * DSAE + e] = zv;
            const int p = atomicAdd(&s_cnt, 1);
            g_idx[b * KTOP + p] = e;
            g_val[b * KTOP + p] = zv;
        } else {
            z_out[(size_t)b * DSAE + e] = 0.f;   // band entries fixed up later
            if (v >= lo_thr) {
                const int q = atomicAdd(&g_bcnt[b], 1);
                if (q < MAXB) g_bidx[b][q] = e;
            }
        }
    }
    __syncthreads();
    if (tid == 0) g_scnt[b] = s_cnt;
}

// ---------------------------------------------------------------------------
// Kernel 3: exact rescoring of band candidates
// ---------------------------------------------------------------------------
__global__ __launch_bounds__(256)
void rescore_kernel(const float* __restrict__ x,
                    const float* __restrict__ W,
                    const float* __restrict__ bias)
{
    const int slot = blockIdx.x;
    const int b    = blockIdx.y;
    int cnt = g_bcnt[b];
    if (cnt > MAXB) cnt = MAXB;
    if (slot >= cnt) return;

    __shared__ float wsum[8];
    const int tid  = threadIdx.x;
    const int col  = g_bidx[b][slot];
    const float* xr = x + (size_t)b * KDIM;
    const float* wc = W + col;

    float s = 0.f;
#pragma unroll
    for (int i = 0; i < KDIM / 256; i++) {
        const int k = tid + i * 256;
        s = fmaf(xr[k], __ldg(&wc[(size_t)k * DSAE]), s);
    }
#pragma unroll
    for (int o = 16; o > 0; o >>= 1) s += __shfl_down_sync(0xffffffffu, s, o);
    if ((tid & 31) == 0) wsum[tid >> 5] = s;
    __syncthreads();
    if (tid == 0) {
        float tot = 0.f;
#pragma unroll
        for (int w = 0; w < 8; w++) tot += wsum[w];
        g_bval[b][slot] = tot + bias[col];
    }
}

// ---------------------------------------------------------------------------
// Kernel 4: fixup — rank band entries by exact score, fill remaining slots
// ---------------------------------------------------------------------------
__global__ __launch_bounds__(MAXB)
void fixup_kernel(float* __restrict__ z_out)
{
    __shared__ int   bi[MAXB];
    __shared__ float bv[MAXB];

    const int b   = blockIdx.x;
    const int tid = threadIdx.x;
    int cnt = g_bcnt[b];
    if (cnt > MAXB) cnt = MAXB;
    const int scnt = g_scnt[b];
    const int rem  = KTOP - scnt;

    if (tid < cnt) { bi[tid] = g_bidx[b][tid]; bv[tid] = g_bval[b][tid]; }
    __syncthreads();

    if (tid < cnt) {
        const int   mi = bi[tid];
        const float mv = bv[tid];
        int rank = 0;
        for (int j = 0; j < cnt; j++)
            rank += (bv[j] > mv) || (bv[j] == mv && bi[j] < mi);
        if (rank < rem) {
            const float zv = fmaxf(mv, 0.f);
            z_out[(size_t)b * DSAE + mi] = zv;
            const int pos = scnt + rank;
            g_idx[b * KTOP + pos] = mi;
            g_val[b * KTOP + pos] = zv;
        }
    }
}

// ---------------------------------------------------------------------------
// Kernel 5: sparse decode + basis combine + x_hat + loss
// ---------------------------------------------------------------------------
__global__ __launch_bounds__(256)
void decode_kernel(const float* __restrict__ x,
                   const float* __restrict__ Wb,
                   const float* __restrict__ alpha,
                   const float* __restrict__ b_dec,
                   float* __restrict__ xhat,
                   float* __restrict__ loss)
{
    __shared__ int   sidx[KTOP];
    __shared__ float sval[KTOP];
    __shared__ float salpha[TDIM * KBASIS];
    __shared__ float warpsum[8];

    const int b = blockIdx.x, tid = threadIdx.x;
    if (tid < KTOP)          { sidx[tid] = g_idx[b * KTOP + tid]; sval[tid] = g_val[b * KTOP + tid]; }
    if (tid < TDIM * KBASIS) { salpha[tid] = alpha[tid]; }
    __syncthreads();

    float acc[KBASIS][3];
#pragma unroll
    for (int k3 = 0; k3 < KBASIS; k3++)
#pragma unroll
        for (int dd = 0; dd < 3; dd++) acc[k3][dd] = 0.f;

    for (int j = 0; j < KTOP; j++) {
        const float v = sval[j];
        if (v == 0.f) continue;
        const int s = sidx[j];
        const float* wr = Wb + (size_t)s * DIN;
#pragma unroll
        for (int k3 = 0; k3 < KBASIS; k3++) {
            const float* w = wr + (size_t)k3 * DSAE * DIN;
#pragma unroll
            for (int dd = 0; dd < 3; dd++)
                acc[k3][dd] = fmaf(v, __ldg(&w[tid + dd * 256]), acc[k3][dd]);
        }
    }

    float lsum = 0.f;
#pragma unroll
    for (int t = 0; t < TDIM; t++) {
        const float a0 = salpha[t * KBASIS + 0];
        const float a1 = salpha[t * KBASIS + 1];
        const float a2 = salpha[t * KBASIS + 2];
#pragma unroll
        for (int dd = 0; dd < 3; dd++) {
            const int d = tid + dd * 256;
            const size_t off = ((size_t)b * TDIM + t) * DIN + d;
            const float xh = a0 * acc[0][dd] + a1 * acc[1][dd] + a2 * acc[2][dd]
                           + b_dec[t * DIN + d];
            xhat[off] = xh;
            const float diff = xh - x[off];
            lsum = fmaf(diff, diff, lsum);
        }
    }

#pragma unroll
    for (int o = 16; o > 0; o >>= 1) lsum += __shfl_down_sync(0xffffffffu, lsum, o);
    if ((tid & 31) == 0) warpsum[tid >> 5] = lsum;
    __syncthreads();
    if (tid == 0) {
        float s = 0.f;
#pragma unroll
        for (int w = 0; w < 8; w++) s += warpsum[w];
        atomicAdd(loss, s * (1.0f / (float)(BSZ * TDIM)));
    }
}

// ---------------------------------------------------------------------------
// kernel_launch: inputs = [x, W_enc, b_enc, W_base, alpha, b_dec, k]
// output (f32, concat): [recon_loss(1), x_hat(B*T*DIN), z(B*DSAE)]
// ---------------------------------------------------------------------------
extern "C" void kernel_launch(void* const* d_in, const int* in_sizes, int n_in,
                              void* d_out, int out_size)
{
    const float* x      = (const float*)d_in[0];
    const float* W_enc  = (const float*)d_in[1];
    const float* b_enc  = (const float*)d_in[2];
    const float* W_base = (const float*)d_in[3];
    const float* alpha  = (const float*)d_in[4];
    const float* b_dec  = (const float*)d_in[5];

    float* out  = (float*)d_out;
    float* loss = out;
    float* xhat = out + 1;
    float* z    = out + 1 + (size_t)BSZ * TDIM * DIN;

    cudaMemsetAsync(loss, 0, sizeof(float));

    // pad launch count: harness poison=0, memset=1, nops=2..4 -> gemm at 5
    nop_kernel<<<1, 1>>>();
    nop_kernel<<<1, 1>>>();
    nop_kernel<<<1, 1>>>();

    cudaFuncSetAttribute(enc_gemm,
                         cudaFuncAttributeMaxDynamicSharedMemorySize, SMEM_B);
    dim3 gemm_grid(BSZ / 128, DSAE / 128, 2);   // (8, 128, 2): split-K
    enc_gemm<<<gemm_grid, 128, SMEM_B>>>(x, W_enc);

    cudaFuncSetAttribute(topk_kernel,
                         cudaFuncAttributeMaxDynamicSharedMemorySize,
                         DSAE * (int)sizeof(unsigned));
    topk_kernel<<<BSZ, 256, DSAE * sizeof(unsigned)>>>(z, b_enc);

    rescore_kernel<<<dim3(MAXB, BSZ), 256>>>(x, W_enc, b_enc);
    fixup_kernel<<<BSZ, MAXB>>>(z);

    decode_kernel<<<BSZ, 256>>>(x, W_base, alpha, b_dec, xhat, loss);
}